// round 4
// baseline (speedup 1.0000x reference)
#include <cuda_runtime.h>
#include <cstdint>

// ---------------------------------------------------------------------------
// HDCTokenEncoder: out[b,i,d] = item_memory[tok[b,i]][(d - i) mod D] * (1/sqrt(D))
// item_memory entries are exactly +/-1 => row L2 norm == sqrt(D) == 100 exactly,
// so normalization is the constant 0.01f (pre-applied while staging SMEM).
//
// R4 design: a cyclic roll is two contiguous chunks. Block (t, y) handles
// positions { i : i % 16 == y } of token t; all share m = r mod 4 = y & 3.
// Stage T[d] = 0.01 * row[(d - m) mod D] once (pre-rotated by m floats), then
// every output row is T rotated by 4k floats (16B multiple):
//     out[0   .. 4k) <- T[D-4k .. D)      (16k bytes,  16B aligned)
//     out[4k  .. D ) <- T[0    .. D-4k)   (rest,       16B aligned)
// Both chunks are issued as cp.async.bulk shared->global (TMA engine): the
// SM's L1/LSU does ZERO work per output row; stores bypass L1 entirely.
// ---------------------------------------------------------------------------

#define HDC_D      10000
#define HDC_D4     2500              // D / 4
#define HDC_ROWB   40000             // row bytes (multiple of 16)
#define HDC_S      2048              // sequence length (power of two)
#define HDC_BS     16384             // B * S
#define HDC_V      256
#define PSPLIT     16                // position classes (multiple of 4!)
#define CAND       (HDC_BS / PSPLIT) // 1024 candidates per block
#define NTHR       512

__device__ __forceinline__ uint32_t smem_u32(const void* p) {
    return (uint32_t)__cvta_generic_to_shared(p);
}

__device__ __forceinline__ void bulk_s2g(void* dst, uint32_t src_smem, uint32_t bytes) {
    asm volatile(
        "cp.async.bulk.global.shared::cta.bulk_group [%0], [%1], %2;"
        :: "l"(dst), "r"(src_smem), "r"(bytes) : "memory");
}

template <int OFS>
__device__ __forceinline__ float4 blend(float4 A, float4 B) {
    if (OFS == 0) return A;
    if (OFS == 1) return make_float4(A.y, A.z, A.w, B.x);
    if (OFS == 2) return make_float4(A.z, A.w, B.x, B.y);
    return make_float4(A.w, B.x, B.y, B.z);
}

// Stage T[d] = 0.01 * s[(d - m) mod D] into smem (quad g covers floats 4g..4g+3).
template <int OFS>  // OFS = (-m) mod 4, the intra-quad start within the source
__device__ __forceinline__ void stage(const float4* __restrict__ sq,
                                      float4* __restrict__ T4, int m) {
    const float scale = 0.01f;
    for (int g = threadIdx.x; g < HDC_D4; g += NTHR) {
        int s0 = 4 * g - m;
        if (s0 < 0) s0 += HDC_D;
        int qa = s0 >> 2;
        float4 v;
        if (OFS == 0) {
            v = __ldg(&sq[qa]);
        } else {
            int qb = qa + 1;
            if (qb == HDC_D4) qb = 0;
            v = blend<OFS>(__ldg(&sq[qa]), __ldg(&sq[qb]));
        }
        v.x *= scale; v.y *= scale; v.z *= scale; v.w *= scale;
        T4[g] = v;
    }
}

__global__ __launch_bounds__(NTHR) void k_encode(const int* __restrict__ tok,
                                                 const float* __restrict__ im,
                                                 float* __restrict__ out) {
    __shared__ float4 T4[HDC_D4];      // 40 KB pre-rotated, pre-scaled row
    __shared__ int    list[CAND];      // matching flat positions
    __shared__ int    nmatch;

    const int t = blockIdx.x;          // token id
    const int y = blockIdx.y;          // position class: i % 16 == y
    const int m = y & 3;               // shared r mod 4 for all rows here

    if (threadIdx.x == 0) nmatch = 0;
    __syncthreads();

    // Phase 1: find positions (candidate i = y + 16*j); token array is L2-hot.
    #pragma unroll
    for (int j = threadIdx.x; j < CAND; j += NTHR) {
        int i = y + PSPLIT * j;
        if (__ldg(&tok[i]) == t) {
            int k = atomicAdd(&nmatch, 1);
            list[k] = i;
        }
    }
    __syncthreads();

    const int n = nmatch;
    if (n == 0) return;

    // Phase 2: stage the pre-rotated row. ofs = (-m) mod 4 is compile-selected.
    const float4* sq = reinterpret_cast<const float4*>(im + (size_t)t * HDC_D);
    switch ((4 - m) & 3) {
        case 0: stage<0>(sq, T4, m); break;
        case 1: stage<1>(sq, T4, m); break;
        case 2: stage<2>(sq, T4, m); break;
        default: stage<3>(sq, T4, m); break;
    }
    // Order smem writes before async-proxy (TMA) reads, then block-wide sync.
    asm volatile("fence.proxy.async.shared::cta;" ::: "memory");
    __syncthreads();

    // Phase 3: each row = two contiguous bulk copies (TMA S2G, L1 untouched).
    const uint32_t s_base = smem_u32(T4);
    bool issued = false;
    for (int p = threadIdx.x; p < n; p += NTHR) {
        const int bs = list[p];
        const int r  = bs & (HDC_S - 1);            // r mod 4 == m by construction
        const uint32_t c1 = (uint32_t)(r >> 2) * 16u;   // bytes of leading chunk
        char* dst = reinterpret_cast<char*>(out) + (size_t)bs * HDC_ROWB;
        if (c1) bulk_s2g(dst, s_base + (HDC_ROWB - c1), c1);
        bulk_s2g(dst + c1, s_base, HDC_ROWB - c1);
        issued = true;
    }
    if (issued) {
        asm volatile("cp.async.bulk.commit_group;" ::: "memory");
        asm volatile("cp.async.bulk.wait_group 0;" ::: "memory");
    }
}

extern "C" void kernel_launch(void* const* d_in, const int* in_sizes, int n_in,
                              void* d_out, int out_size) {
    const int*   tok = (const int*)d_in[0];     // (B, S) int32
    const float* im  = (const float*)d_in[1];   // (V, D) float32
    float*       out = (float*)d_out;           // (B, S, D) float32
    (void)in_sizes; (void)n_in; (void)out_size;

    dim3 grid(HDC_V, PSPLIT);
    k_encode<<<grid, NTHR>>>(tok, im, out);
}

// round 5
// speedup vs baseline: 1.1200x; 1.1200x over previous
#include <cuda_runtime.h>
#include <cstdint>

// ---------------------------------------------------------------------------
// HDCTokenEncoder: out[b,i,d] = item_memory[tok[b,i]][(d - i) mod D] * (1/sqrt(D))
// item_memory entries are exactly +/-1 => row L2 norm == sqrt(D) == 100 exactly,
// so normalization is the constant 0.01f (applied once while staging SMEM).
//
// R5 design (best of R3+R4): block (t, y) handles positions { i : i % 16 == y }
// of token t; they all share m = r mod 4 = y & 3. Stage the PRE-ROTATED row
// T[d] = 0.01 * row[(d - m) mod D] once (blend cost paid once per block), so
// every output row is T rotated by a whole number of float4 quads:
//     out quad g = T quad (g - (r - m)/4) mod D4
// Hot loop is 1 aligned LDS.128 + 1 streaming STG.128 per quad (vs 2 LDS + 1
// STG in R3) -- cuts L1 wavefronts by a third; DRAM write stream is binder.
// ---------------------------------------------------------------------------

#define HDC_D      10000
#define HDC_D4     2500              // D / 4
#define HDC_S      2048              // sequence length (power of two)
#define HDC_BS     16384             // B * S
#define HDC_V      256
#define PSPLIT     16                // position classes (multiple of 4!)
#define CAND       (HDC_BS / PSPLIT) // 1024 candidates per block
#define NTHR       512

template <int OFS>
__device__ __forceinline__ float4 blend(float4 A, float4 B) {
    if (OFS == 0) return A;
    if (OFS == 1) return make_float4(A.y, A.z, A.w, B.x);
    if (OFS == 2) return make_float4(A.z, A.w, B.x, B.y);
    return make_float4(A.w, B.x, B.y, B.z);
}

// Stage T[d] = 0.01 * s[(d - m) mod D]; OFS = (-m) mod 4.
template <int OFS>
__device__ __forceinline__ void stage(const float4* __restrict__ sq,
                                      float4* __restrict__ T4, int m) {
    const float scale = 0.01f;
    for (int g = threadIdx.x; g < HDC_D4; g += NTHR) {
        int s0 = 4 * g - m;
        if (s0 < 0) s0 += HDC_D;
        int qa = s0 >> 2;
        float4 v;
        if (OFS == 0) {
            v = __ldg(&sq[qa]);
        } else {
            int qb = qa + 1;
            if (qb == HDC_D4) qb = 0;
            v = blend<OFS>(__ldg(&sq[qa]), __ldg(&sq[qb]));
        }
        v.x *= scale; v.y *= scale; v.z *= scale; v.w *= scale;
        T4[g] = v;
    }
}

__global__ __launch_bounds__(NTHR) void k_encode(const int* __restrict__ tok,
                                                 const float* __restrict__ im,
                                                 float* __restrict__ out) {
    __shared__ float4 T4[HDC_D4];      // 40 KB pre-rotated, pre-scaled row
    __shared__ int    list[CAND];      // matching flat positions
    __shared__ int    nmatch;

    const int t = blockIdx.x;          // token id
    const int y = blockIdx.y;          // position class: i % 16 == y
    const int m = y & 3;               // shared r mod 4 for all rows here

    if (threadIdx.x == 0) nmatch = 0;
    __syncthreads();

    // Phase 1: find positions (candidate i = y + 16*j); token array is L2-hot.
    #pragma unroll
    for (int j = threadIdx.x; j < CAND; j += NTHR) {
        int i = y + PSPLIT * j;
        if (__ldg(&tok[i]) == t) {
            int k = atomicAdd(&nmatch, 1);
            list[k] = i;
        }
    }
    __syncthreads();

    const int n = nmatch;
    if (n == 0) return;

    // Phase 2: stage the pre-rotated, pre-scaled row (blend paid once).
    const float4* sq = reinterpret_cast<const float4*>(im + (size_t)t * HDC_D);
    switch ((4 - m) & 3) {
        case 0: stage<0>(sq, T4, m); break;
        case 1: stage<1>(sq, T4, m); break;
        case 2: stage<2>(sq, T4, m); break;
        default: stage<3>(sq, T4, m); break;
    }
    __syncthreads();

    // Phase 3: emit rows; each is a whole-quad rotation of T.
    for (int p = 0; p < n; ++p) {
        const int bs = list[p];
        const int r  = bs & (HDC_S - 1);        // r mod 4 == m by construction
        const int q0 = (r - m) >> 2;            // quad rotation amount
        float4* dst = reinterpret_cast<float4*>(out + (size_t)bs * HDC_D);

        int qa = (int)threadIdx.x - q0;
        if (qa < 0) qa += HDC_D4;
        for (int g = threadIdx.x; g < HDC_D4; g += NTHR) {
            __stcs(dst + g, T4[qa]);
            qa += NTHR;
            if (qa >= HDC_D4) qa -= HDC_D4;
        }
    }
}

extern "C" void kernel_launch(void* const* d_in, const int* in_sizes, int n_in,
                              void* d_out, int out_size) {
    const int*   tok = (const int*)d_in[0];     // (B, S) int32
    const float* im  = (const float*)d_in[1];   // (V, D) float32
    float*       out = (float*)d_out;           // (B, S, D) float32
    (void)in_sizes; (void)n_in; (void)out_size;

    dim3 grid(HDC_V, PSPLIT);
    k_encode<<<grid, NTHR>>>(tok, im, out);
}